// round 2
// baseline (speedup 1.0000x reference)
#include <cuda_runtime.h>
#include <cuda_bf16.h>
#include <cstddef>

// Problem constants
#define BATCH 4
#define SEQ   2048
#define DIM   1024
#define HEADS 16
#define DH    64           // DIM / HEADS
#define MROWS (BATCH*SEQ)  // 8192
#define SCALE 0.03125f     // 1/sqrt(1024)

// Scratch (allocation-free rule: __device__ globals)
__device__ float g_Q[(size_t)MROWS * DIM];
__device__ float g_K[(size_t)MROWS * DIM];
__device__ float g_V[(size_t)MROWS * DIM];
__device__ float g_C[(size_t)MROWS * DIM];

// ---------------------------------------------------------------------------
// SGEMM: C[M,N] = A[M,K] * B[K,N], fp32, M%128==0, N%128==0, K%8==0
// 128x128 tile, BK=8, 256 threads, 8x8 per thread.
// ---------------------------------------------------------------------------
__global__ __launch_bounds__(256) void sgemm128(const float* __restrict__ A,
                                                const float* __restrict__ B,
                                                float* __restrict__ C,
                                                int M, int N, int K) {
    const int BM = 128, BN = 128, BK = 8;
    __shared__ float sA[BK][BM];
    __shared__ float sB[BK][BN];

    int tid = threadIdx.x;
    int bx = blockIdx.x, by = blockIdx.y;

    int arow = tid >> 1;            // 0..127
    int acol = (tid & 1) * 4;       // 0 or 4
    int brow = tid >> 5;            // 0..7
    int bcol = (tid & 31) * 4;      // 0..124

    const float* Ap = A + (size_t)(by * BM + arow) * K + acol;
    const float* Bp = B + (size_t)brow * N + bx * BN + bcol;

    int ty = tid >> 4;              // 0..15
    int tx = tid & 15;              // 0..15

    float acc[8][8];
#pragma unroll
    for (int i = 0; i < 8; i++)
#pragma unroll
        for (int j = 0; j < 8; j++) acc[i][j] = 0.f;

    for (int k0 = 0; k0 < K; k0 += BK) {
        float4 a4 = *(const float4*)Ap;  Ap += BK;
        float4 b4 = *(const float4*)Bp;  Bp += (size_t)BK * N;

        __syncthreads();
        sA[acol + 0][arow] = a4.x;
        sA[acol + 1][arow] = a4.y;
        sA[acol + 2][arow] = a4.z;
        sA[acol + 3][arow] = a4.w;
        *(float4*)&sB[brow][bcol] = b4;
        __syncthreads();

#pragma unroll
        for (int kk = 0; kk < BK; kk++) {
            float ra[8], rb[8];
#pragma unroll
            for (int i = 0; i < 8; i++) ra[i] = sA[kk][ty * 8 + i];
#pragma unroll
            for (int j = 0; j < 8; j++) rb[j] = sB[kk][tx * 8 + j];
#pragma unroll
            for (int i = 0; i < 8; i++)
#pragma unroll
                for (int j = 0; j < 8; j++)
                    acc[i][j] += ra[i] * rb[j];
        }
    }

#pragma unroll
    for (int i = 0; i < 8; i++) {
        float* Cp = C + (size_t)(by * BM + ty * 8 + i) * N + bx * BN + tx * 8;
        ((float4*)Cp)[0] = make_float4(acc[i][0], acc[i][1], acc[i][2], acc[i][3]);
        ((float4*)Cp)[1] = make_float4(acc[i][4], acc[i][5], acc[i][6], acc[i][7]);
    }
}

// ---------------------------------------------------------------------------
// Flash attention: one thread = one query row. Q row + O accumulator in regs.
// K/V tiles of KT rows staged in smem (reads are warp-broadcast).
// grid = (SEQ/128, HEADS, BATCH), block = 128.
// ---------------------------------------------------------------------------
#define KT 16

__global__ __launch_bounds__(128) void attn_kernel(const float* __restrict__ Q,
                                                   const float* __restrict__ K,
                                                   const float* __restrict__ V,
                                                   float* __restrict__ O) {
    __shared__ float sK[KT][DH];
    __shared__ float sV[KT][DH];

    int b = blockIdx.z;
    int h = blockIdx.y;
    int t = threadIdx.x;
    int qrow = blockIdx.x * 128 + t;

    const float* qp = Q + ((size_t)(b * SEQ + qrow)) * DIM + h * DH;
    float q[DH], o[DH];
#pragma unroll
    for (int i = 0; i < DH / 4; i++) {
        float4 v4 = ((const float4*)qp)[i];
        q[4 * i + 0] = v4.x; q[4 * i + 1] = v4.y;
        q[4 * i + 2] = v4.z; q[4 * i + 3] = v4.w;
    }
#pragma unroll
    for (int d = 0; d < DH; d++) o[d] = 0.f;

    float m = -1e30f, l = 0.f;
    const size_t kbase = (size_t)b * SEQ * DIM + (size_t)h * DH;

    for (int k0 = 0; k0 < SEQ; k0 += KT) {
        // Stage K/V tile: KT*DH = 1024 floats = 256 float4; 128 threads -> 2 each
#pragma unroll
        for (int i = 0; i < 2; i++) {
            int slot = t + i * 128;          // 0..255
            int r  = slot >> 4;              // 0..15
            int c4 = slot & 15;              // 0..15
            size_t rowoff = kbase + (size_t)(k0 + r) * DIM;
            ((float4*)&sK[r][0])[c4] = *((const float4*)(K + rowoff) + c4);
            ((float4*)&sV[r][0])[c4] = *((const float4*)(V + rowoff) + c4);
        }
        __syncthreads();

        float s[KT];
        float mx = m;
#pragma unroll
        for (int k = 0; k < KT; k++) {
            float acc = 0.f;
#pragma unroll
            for (int d = 0; d < DH; d++) acc += q[d] * sK[k][d];
            s[k] = acc * SCALE;
            mx = fmaxf(mx, s[k]);
        }

        float corr = __expf(m - mx);   // first tile: exp(-huge)=0
        m = mx;
        l *= corr;
#pragma unroll
        for (int d = 0; d < DH; d++) o[d] *= corr;

#pragma unroll
        for (int k = 0; k < KT; k++) {
            float p = __expf(s[k] - m);
            l += p;
#pragma unroll
            for (int d = 0; d < DH; d++) o[d] += p * sV[k][d];
        }
        __syncthreads();
    }

    float inv = 1.f / l;
    float* op = O + ((size_t)(b * SEQ + qrow)) * DIM + h * DH;
#pragma unroll
    for (int i = 0; i < DH / 4; i++) {
        ((float4*)op)[i] = make_float4(o[4 * i + 0] * inv, o[4 * i + 1] * inv,
                                       o[4 * i + 2] * inv, o[4 * i + 3] * inv);
    }
}

// ---------------------------------------------------------------------------
// kernel_launch: x,WQ,WK,WV,WO -> out
// ---------------------------------------------------------------------------
extern "C" void kernel_launch(void* const* d_in, const int* in_sizes, int n_in,
                              void* d_out, int out_size) {
    const float* x  = (const float*)d_in[0];
    const float* WQ = (const float*)d_in[1];
    const float* WK = (const float*)d_in[2];
    const float* WV = (const float*)d_in[3];
    const float* WO = (const float*)d_in[4];
    float* out = (float*)d_out;

    float *pQ, *pK, *pV, *pC;
    cudaGetSymbolAddress((void**)&pQ, g_Q);
    cudaGetSymbolAddress((void**)&pK, g_K);
    cudaGetSymbolAddress((void**)&pV, g_V);
    cudaGetSymbolAddress((void**)&pC, g_C);

    dim3 ggrid(DIM / 128, MROWS / 128);   // (8, 64)
    sgemm128<<<ggrid, 256>>>(x, WQ, pQ, MROWS, DIM, DIM);
    sgemm128<<<ggrid, 256>>>(x, WK, pK, MROWS, DIM, DIM);
    sgemm128<<<ggrid, 256>>>(x, WV, pV, MROWS, DIM, DIM);

    dim3 agrid(SEQ / 128, HEADS, BATCH);  // (16, 16, 4)
    attn_kernel<<<agrid, 128>>>(pQ, pK, pV, pC);

    sgemm128<<<ggrid, 256>>>(pC, WO, out, MROWS, DIM, DIM);
}